// round 1
// baseline (speedup 1.0000x reference)
#include <cuda_runtime.h>
#include <cuda_bf16.h>
#include <math.h>

// Problem constants
#define NN 100000      // nodes / entities
#define EE 500000      // edges
#define RR 8           // relations
#define DD 128         // hidden
#define KA 1024        // R*D (stacked-W K)
#define KT 1152        // KA + D (root appended)

// -------- scratch (device globals; no allocation allowed) --------
__device__ float g_x  [(size_t)NN * DD];        // layer input  (51.2 MB)
__device__ float g_y  [(size_t)NN * DD];        // layer-1 out  (51.2 MB)
__device__ float g_A  [(size_t)NN * KA];        // per-(node,rel) mean msgs (409.6 MB)
__device__ float g_inv[(size_t)NN * RR];        // 1/count per (node,rel)
__device__ int   g_cnt[(size_t)NN * RR];

// ---------------- kernels ----------------

// x[n] = emb[x_ids[n]] ; one warp per node, one float4 per lane
__global__ void k_gather(const int* __restrict__ ids, const float* __restrict__ emb) {
    int t = blockIdx.x * blockDim.x + threadIdx.x;   // N*32 threads
    int n = t >> 5, l = t & 31;
    if (n < NN) {
        float4 v = ((const float4*)(emb + (size_t)ids[n] * DD))[l];
        ((float4*)(g_x + (size_t)n * DD))[l] = v;
    }
}

__global__ void k_zero_cnt() {
    int t = blockIdx.x * blockDim.x + threadIdx.x;
    if (t < NN * RR) g_cnt[t] = 0;
}

__global__ void k_count(const int* __restrict__ ei, const int* __restrict__ et) {
    int e = blockIdx.x * blockDim.x + threadIdx.x;
    if (e < EE) {
        int dst = ei[EE + e];
        int r   = et[e];
        atomicAdd(&g_cnt[dst * RR + r], 1);
    }
}

__global__ void k_inv() {
    int t = blockIdx.x * blockDim.x + threadIdx.x;
    if (t < NN * RR) {
        int c = g_cnt[t];
        g_inv[t] = c > 0 ? 1.0f / (float)c : 0.0f;
    }
}

__global__ void k_zeroA() {
    size_t t = (size_t)blockIdx.x * blockDim.x + threadIdx.x;   // NN*KA/4 threads
    ((float4*)g_A)[t] = make_float4(0.f, 0.f, 0.f, 0.f);
}

// scatter: A[dst, r*128 + :] += x[src,:] * inv(dst,r)   (one warp per edge)
// sel: 0 -> read g_x, 1 -> read g_y
__global__ void k_scatter(const int* __restrict__ ei, const int* __restrict__ et, int sel) {
    int t = blockIdx.x * blockDim.x + threadIdx.x;   // E*32 threads
    int e = t >> 5, l = t & 31;
    if (e >= EE) return;
    const float* xin = sel ? g_y : g_x;
    int src = ei[e];
    int dst = ei[EE + e];
    int r   = et[e];
    float inv = g_inv[dst * RR + r];
    float4 v = __ldg((const float4*)(xin + (size_t)src * DD) + l);
    v.x *= inv; v.y *= inv; v.z *= inv; v.w *= inv;
    float* p = g_A + ((size_t)dst * RR + r) * DD + l * 4;
    asm volatile("red.global.add.v4.f32 [%0], {%1, %2, %3, %4};"
                 :: "l"(p), "f"(v.x), "f"(v.y), "f"(v.z), "f"(v.w) : "memory");
}

// C[n,f] = sum_k A[n,k]*W[k,f] + sum_d x[n,d]*root[d,f] + b[f]
// ACT 0 = relu (layer 1, writes g_y), ACT 1 = sigmoid (layer 2, writes outp)
#define BM 128
#define BN 128
#define BK 8
template<int ACT>
__global__ __launch_bounds__(256, 2)
void k_gemm(const float* __restrict__ W, const float* __restrict__ rootM,
            const float* __restrict__ bias, float* __restrict__ outp) {
    __shared__ float As[BK][BM];
    __shared__ float Bs[BK][BN];

    const float* xin = (ACT == 0) ? g_x : g_y;   // root-term input for this layer

    int tid  = threadIdx.x;
    int row0 = blockIdx.x * BM;
    int tx   = tid & 15;      // 0..15 -> col block of 8
    int ty   = tid >> 4;      // 0..15 -> row block of 8

    int lm = tid >> 1;            // A loader: row 0..127
    int lk = (tid & 1) * 4;       // A loader: k offset 0 or 4
    int bk  = tid >> 5;           // B loader: k row 0..7
    int bn4 = (tid & 31) * 4;     // B loader: col*4

    float acc[8][8];
#pragma unroll
    for (int i = 0; i < 8; i++)
#pragma unroll
        for (int j = 0; j < 8; j++) acc[i][j] = 0.f;

    for (int kk = 0; kk < KT; kk += BK) {
        // ---- load A tile (from g_A for k<1024, from xin for the root chunk) ----
        int arow = row0 + lm;
        float4 av = make_float4(0.f, 0.f, 0.f, 0.f);
        if (arow < NN) {
            if (kk < KA) av = *(const float4*)(g_A + (size_t)arow * KA + kk + lk);
            else         av = *(const float4*)(xin + (size_t)arow * DD + (kk - KA) + lk);
        }
        As[lk + 0][lm] = av.x;
        As[lk + 1][lm] = av.y;
        As[lk + 2][lm] = av.z;
        As[lk + 3][lm] = av.w;
        // ---- load B tile (W for k<1024, root for the rest) ----
        const float* bsrc = (kk < KA) ? (W + (size_t)kk * DD)
                                      : (rootM + (size_t)(kk - KA) * DD);
        float4 bv = *(const float4*)(bsrc + bk * DD + bn4);
        *(float4*)&Bs[bk][bn4] = bv;
        __syncthreads();

#pragma unroll
        for (int k = 0; k < BK; k++) {
            float ra[8], rb[8];
            *(float4*)&ra[0] = *(const float4*)&As[k][ty * 8];
            *(float4*)&ra[4] = *(const float4*)&As[k][ty * 8 + 4];
            *(float4*)&rb[0] = *(const float4*)&Bs[k][tx * 8];
            *(float4*)&rb[4] = *(const float4*)&Bs[k][tx * 8 + 4];
#pragma unroll
            for (int i = 0; i < 8; i++)
#pragma unroll
                for (int j = 0; j < 8; j++)
                    acc[i][j] = fmaf(ra[i], rb[j], acc[i][j]);
        }
        __syncthreads();
    }

    // ---- epilogue ----
#pragma unroll
    for (int i = 0; i < 8; i++) {
        int row = row0 + ty * 8 + i;
        if (row >= NN) break;
#pragma unroll
        for (int j = 0; j < 8; j++) {
            int col = tx * 8 + j;
            float v = acc[i][j] + bias[col];
            float r;
            if (ACT == 0) { r = fmaxf(v, 0.f);           g_y[(size_t)row * DD + col] = r; }
            else          { r = 1.0f / (1.0f + expf(-v)); outp[(size_t)row * DD + col] = r; }
        }
    }
}

// ---------------- launch ----------------
extern "C" void kernel_launch(void* const* d_in, const int* in_sizes, int n_in,
                              void* d_out, int out_size) {
    const int*   x_ids = (const int*)  d_in[0];
    const int*   ei    = (const int*)  d_in[1];   // [2, E]: src row then dst row
    const int*   et    = (const int*)  d_in[2];
    const float* emb   = (const float*)d_in[3];
    const float* W1    = (const float*)d_in[4];   // [8,128,128] == [1024,128] row-major
    const float* root1 = (const float*)d_in[5];
    const float* b1    = (const float*)d_in[6];
    const float* W2    = (const float*)d_in[7];
    const float* root2 = (const float*)d_in[8];
    const float* b2    = (const float*)d_in[9];
    float*       out   = (float*)d_out;
    (void)in_sizes; (void)n_in; (void)out_size;

    const int T = 256;
    const int gemmBlocks = (NN + BM - 1) / BM;   // 782

    // 0) embedding gather
    k_gather<<<(NN * 32) / T, T>>>(x_ids, emb);
    // 1) counts + inverse (shared by both layers)
    k_zero_cnt<<<(NN * RR + T - 1) / T, T>>>();
    k_count<<<(EE + T - 1) / T, T>>>(ei, et);
    k_inv<<<(NN * RR + T - 1) / T, T>>>();

    // ---- layer 1 ----
    k_zeroA<<<(int)(((size_t)NN * KA / 4) / T), T>>>();
    k_scatter<<<(EE * 32) / T, T>>>(ei, et, /*sel=*/0);
    k_gemm<0><<<gemmBlocks, T>>>(W1, root1, b1, nullptr);   // relu -> g_y

    // ---- layer 2 ----
    k_zeroA<<<(int)(((size_t)NN * KA / 4) / T), T>>>();
    k_scatter<<<(EE * 32) / T, T>>>(ei, et, /*sel=*/1);
    k_gemm<1><<<gemmBlocks, T>>>(W2, root2, b2, out);       // sigmoid -> out
}

// round 2
// speedup vs baseline: 1.5267x; 1.5267x over previous
#include <cuda_runtime.h>
#include <cuda_bf16.h>
#include <math.h>
#include <stdint.h>

// Problem constants
#define NN 100000      // nodes
#define EE 500000      // edges
#define RR 8           // relations
#define DD 128         // hidden
#define KT 1152        // output cols of big GEMM: R*D (relations) + D (root)

// -------- scratch (device globals; no allocation allowed) --------
__device__ __nv_bfloat16 g_xhi[(size_t)NN * DD];     // layer input hi (25.6MB)
__device__ __nv_bfloat16 g_xlo[(size_t)NN * DD];     // layer input lo
__device__ __nv_bfloat16 g_wthi[(size_t)KT * DD];    // transposed weights hi
__device__ __nv_bfloat16 g_wtlo[(size_t)KT * DD];
__device__ float g_h  [(size_t)NN * KT];             // h = x @ Wt (460MB)
__device__ float g_out[(size_t)NN * DD];             // aggregated output (51MB)
__device__ float g_inv[(size_t)NN * RR];
__device__ int   g_cnt[(size_t)NN * RR];

// ---------------- helpers ----------------
__device__ __forceinline__ uint32_t saddr(const void* p) {
    return (uint32_t)__cvta_generic_to_shared(p);
}
__device__ __forceinline__ void ldsm_x4(uint32_t* r, uint32_t addr) {
    asm volatile("ldmatrix.sync.aligned.m8n8.x4.shared.b16 {%0,%1,%2,%3}, [%4];"
                 : "=r"(r[0]), "=r"(r[1]), "=r"(r[2]), "=r"(r[3]) : "r"(addr));
}
__device__ __forceinline__ void mma_bf16(float* c, const uint32_t* a, const uint32_t* b) {
    asm volatile("mma.sync.aligned.m16n8k16.row.col.f32.bf16.bf16.f32 "
                 "{%0,%1,%2,%3}, {%4,%5,%6,%7}, {%8,%9}, {%0,%1,%2,%3};"
                 : "+f"(c[0]), "+f"(c[1]), "+f"(c[2]), "+f"(c[3])
                 : "r"(a[0]), "r"(a[1]), "r"(a[2]), "r"(a[3]), "r"(b[0]), "r"(b[1]));
}
__device__ __forceinline__ void split2(float v, __nv_bfloat16& h, __nv_bfloat16& l) {
    h = __float2bfloat16(v);
    l = __float2bfloat16(v - __bfloat162float(h));
}

// ---------------- prep kernels ----------------

// x = emb[ids], split to bf16 hi/lo. one warp per node, float4 per lane.
__global__ void k_gather_split(const int* __restrict__ ids, const float* __restrict__ emb) {
    int t = blockIdx.x * blockDim.x + threadIdx.x;   // NN*32 threads
    int n = t >> 5, l4 = (t & 31) * 4;
    if (n >= NN) return;
    float4 v = *((const float4*)(emb + (size_t)ids[n] * DD + l4));
    __nv_bfloat16 h0, h1, h2, h3, l0, l1, l2, l3;
    split2(v.x, h0, l0); split2(v.y, h1, l1); split2(v.z, h2, l2); split2(v.w, h3, l3);
    __nv_bfloat162* ph = (__nv_bfloat162*)(g_xhi + (size_t)n * DD + l4);
    __nv_bfloat162* pl = (__nv_bfloat162*)(g_xlo + (size_t)n * DD + l4);
    ph[0] = __nv_bfloat162{h0, h1}; ph[1] = __nv_bfloat162{h2, h3};
    pl[0] = __nv_bfloat162{l0, l1}; pl[1] = __nv_bfloat162{l2, l3};
}

// Wt[c, d]: c<1024 -> W[r=c/128][d][f=c%128]; c>=1024 -> root[d][c-1024]. split hi/lo.
__global__ void k_wsplit(const float* __restrict__ W, const float* __restrict__ rootM) {
    int t = blockIdx.x * blockDim.x + threadIdx.x;   // KT*DD threads
    if (t >= KT * DD) return;
    int c = t >> 7, d = t & 127;
    float v;
    if (c < RR * DD) {
        int r = c >> 7, f = c & 127;
        v = W[((size_t)r * DD + d) * DD + f];
    } else {
        v = rootM[(size_t)d * DD + (c - RR * DD)];
    }
    __nv_bfloat16 h, l; split2(v, h, l);
    g_wthi[t] = h; g_wtlo[t] = l;
}

__global__ void k_zero_cnt() {
    int t = blockIdx.x * blockDim.x + threadIdx.x;
    if (t < NN * RR) g_cnt[t] = 0;
}
__global__ void k_count(const int* __restrict__ ei, const int* __restrict__ et) {
    int e = blockIdx.x * blockDim.x + threadIdx.x;
    if (e < EE) atomicAdd(&g_cnt[ei[EE + e] * RR + et[e]], 1);
}
__global__ void k_inv() {
    int t = blockIdx.x * blockDim.x + threadIdx.x;
    if (t < NN * RR) {
        int c = g_cnt[t];
        g_inv[t] = c > 0 ? 1.0f / (float)c : 0.0f;
    }
}

// ---------------- tensor-core GEMM: h[M=NN, KT] = x[NN,128] @ Wt^T ----------------
// CTA tile 128x128, whole K=128 in SMEM, 8 warps (4x2), warp tile 32x64.
// 3-term bf16 split: hi*hi + hi*lo + lo*hi (fp32 accumulate).
#define PADK 136                   // bf16 elems per smem row (128 + 8 pad)
#define SEG  (128 * PADK)          // one operand plane
#define GEMM_SMEM (4 * SEG * 2)    // bytes: Ahi, Alo, Bhi, Blo

__global__ __launch_bounds__(256, 1)
void k_gemm() {
    extern __shared__ __nv_bfloat16 sm[];
    __nv_bfloat16* Ah = sm;
    __nv_bfloat16* Al = sm + SEG;
    __nv_bfloat16* Bh = sm + 2 * SEG;
    __nv_bfloat16* Bl = sm + 3 * SEG;

    const int tid  = threadIdx.x;
    const int row0 = blockIdx.y * 128;
    const int c0   = blockIdx.x * 128;

    // ---- load tiles (uint4 = 8 bf16) ----
    for (int v = tid; v < 2048; v += 256) {
        int r = v >> 4, cv = (v & 15) << 3;
        int gr = row0 + r;
        uint4 h = make_uint4(0, 0, 0, 0), l = make_uint4(0, 0, 0, 0);
        if (gr < NN) {
            h = *(const uint4*)(g_xhi + (size_t)gr * DD + cv);
            l = *(const uint4*)(g_xlo + (size_t)gr * DD + cv);
        }
        *(uint4*)(Ah + r * PADK + cv) = h;
        *(uint4*)(Al + r * PADK + cv) = l;
    }
    for (int v = tid; v < 2048; v += 256) {
        int r = v >> 4, cv = (v & 15) << 3;
        *(uint4*)(Bh + r * PADK + cv) = *(const uint4*)(g_wthi + (size_t)(c0 + r) * DD + cv);
        *(uint4*)(Bl + r * PADK + cv) = *(const uint4*)(g_wtlo + (size_t)(c0 + r) * DD + cv);
    }
    __syncthreads();

    const int lane = tid & 31, warp = tid >> 5;
    const int wm = warp & 3;        // M: 4 warps * 32 rows
    const int wn = warp >> 2;       // N: 2 warps * 64 cols

    float acc[2][8][4];
#pragma unroll
    for (int i = 0; i < 2; i++)
#pragma unroll
        for (int j = 0; j < 8; j++)
#pragma unroll
            for (int k = 0; k < 4; k++) acc[i][j][k] = 0.f;

    const int a_row  = wm * 32 + (lane & 15);
    const int a_koff = (lane >> 4) * 8;
    const int b_nrow = wn * 64 + (lane & 7) + ((lane >> 3) & 1) * 8;
    const int b_koff = (lane >> 4) * 8;

#pragma unroll
    for (int ks = 0; ks < 8; ks++) {
        const int k0 = ks * 16;
        uint32_t ah[2][4], al[2][4];
#pragma unroll
        for (int mf = 0; mf < 2; mf++) {
            ldsm_x4(ah[mf], saddr(Ah + (a_row + mf * 16) * PADK + k0 + a_koff));
            ldsm_x4(al[mf], saddr(Al + (a_row + mf * 16) * PADK + k0 + a_koff));
        }
#pragma unroll
        for (int np = 0; np < 4; np++) {
            uint32_t bh[4], bl[4];
            ldsm_x4(bh, saddr(Bh + (b_nrow + np * 16) * PADK + k0 + b_koff));
            ldsm_x4(bl, saddr(Bl + (b_nrow + np * 16) * PADK + k0 + b_koff));
#pragma unroll
            for (int sub = 0; sub < 2; sub++) {
                uint32_t bfh[2] = { bh[sub], bh[sub + 2] };
                uint32_t bfl[2] = { bl[sub], bl[sub + 2] };
#pragma unroll
                for (int mf = 0; mf < 2; mf++) {
                    float* c = acc[mf][np * 2 + sub];
                    mma_bf16(c, ah[mf], bfh);   // hi*hi
                    mma_bf16(c, ah[mf], bfl);   // hi*lo
                    mma_bf16(c, al[mf], bfh);   // lo*hi
                }
            }
        }
    }

    // ---- epilogue: write h fp32 ----
#pragma unroll
    for (int mf = 0; mf < 2; mf++) {
#pragma unroll
        for (int nf = 0; nf < 8; nf++) {
            int r = row0 + wm * 32 + mf * 16 + (lane >> 2);
            int c = c0 + wn * 64 + nf * 8 + (lane & 3) * 2;
            float* cc = acc[mf][nf];
            if (r < NN)
                *(float2*)(g_h + (size_t)r * KT + c) = make_float2(cc[0], cc[1]);
            if (r + 8 < NN)
                *(float2*)(g_h + (size_t)(r + 8) * KT + c) = make_float2(cc[2], cc[3]);
        }
    }
}

// ---------------- aggregation ----------------

// out[n,f] = h[n, 1024+f] (root term) + bias[f]
__global__ void k_init_out(const float* __restrict__ bias) {
    int t = blockIdx.x * blockDim.x + threadIdx.x;   // NN*32 threads
    int n = t >> 5, f4 = (t & 31) * 4;
    if (n >= NN) return;
    float4 h = *(const float4*)(g_h + (size_t)n * KT + RR * DD + f4);
    float4 b = *(const float4*)(bias + f4);
    h.x += b.x; h.y += b.y; h.z += b.z; h.w += b.w;
    *(float4*)(g_out + (size_t)n * DD + f4) = h;
}

// out[dst,:] += h[src, r*128 + :] * inv(dst,r). one warp per edge.
__global__ void k_scatter(const int* __restrict__ ei, const int* __restrict__ et) {
    int t = blockIdx.x * blockDim.x + threadIdx.x;   // EE*32 threads
    int e = t >> 5, l = t & 31;
    if (e >= EE) return;
    int src = ei[e];
    int dst = ei[EE + e];
    int r   = et[e];
    float inv = g_inv[dst * RR + r];
    float4 v = __ldg((const float4*)(g_h + (size_t)src * KT + r * DD) + l);
    v.x *= inv; v.y *= inv; v.z *= inv; v.w *= inv;
    float* p = g_out + (size_t)dst * DD + l * 4;
    asm volatile("red.global.add.v4.f32 [%0], {%1, %2, %3, %4};"
                 :: "l"(p), "f"(v.x), "f"(v.y), "f"(v.z), "f"(v.w) : "memory");
}

// layer-1 activation: x_{hi,lo} = split(relu(out))
__global__ void k_act_relu() {
    int t = blockIdx.x * blockDim.x + threadIdx.x;   // NN*32 threads
    if (t >= NN * 32) return;
    float4 v = *(const float4*)(g_out + (size_t)t * 4);
    v.x = fmaxf(v.x, 0.f); v.y = fmaxf(v.y, 0.f);
    v.z = fmaxf(v.z, 0.f); v.w = fmaxf(v.w, 0.f);
    __nv_bfloat16 h0, h1, h2, h3, l0, l1, l2, l3;
    split2(v.x, h0, l0); split2(v.y, h1, l1); split2(v.z, h2, l2); split2(v.w, h3, l3);
    __nv_bfloat162* ph = (__nv_bfloat162*)(g_xhi + (size_t)t * 4);
    __nv_bfloat162* pl = (__nv_bfloat162*)(g_xlo + (size_t)t * 4);
    ph[0] = __nv_bfloat162{h0, h1}; ph[1] = __nv_bfloat162{h2, h3};
    pl[0] = __nv_bfloat162{l0, l1}; pl[1] = __nv_bfloat162{l2, l3};
}

// layer-2 activation: out = sigmoid(g_out)
__global__ void k_sigmoid(float* __restrict__ outp) {
    int t = blockIdx.x * blockDim.x + threadIdx.x;   // NN*32 threads
    if (t >= NN * 32) return;
    float4 v = *(const float4*)(g_out + (size_t)t * 4);
    v.x = 1.0f / (1.0f + __expf(-v.x));
    v.y = 1.0f / (1.0f + __expf(-v.y));
    v.z = 1.0f / (1.0f + __expf(-v.z));
    v.w = 1.0f / (1.0f + __expf(-v.w));
    *(float4*)(outp + (size_t)t * 4) = v;
}

// ---------------- launch ----------------
extern "C" void kernel_launch(void* const* d_in, const int* in_sizes, int n_in,
                              void* d_out, int out_size) {
    const int*   x_ids = (const int*)  d_in[0];
    const int*   ei    = (const int*)  d_in[1];   // [2, E]: src row then dst row
    const int*   et    = (const int*)  d_in[2];
    const float* emb   = (const float*)d_in[3];
    const float* W1    = (const float*)d_in[4];
    const float* root1 = (const float*)d_in[5];
    const float* b1    = (const float*)d_in[6];
    const float* W2    = (const float*)d_in[7];
    const float* root2 = (const float*)d_in[8];
    const float* b2    = (const float*)d_in[9];
    float*       out   = (float*)d_out;
    (void)in_sizes; (void)n_in; (void)out_size;

    cudaFuncSetAttribute(k_gemm, cudaFuncAttributeMaxDynamicSharedMemorySize, GEMM_SMEM);

    const int T = 256;
    dim3 gemmGrid(KT / 128, (NN + 127) / 128);   // (9, 782)

    // prep
    k_gather_split<<<(NN * 32) / T, T>>>(x_ids, emb);
    k_zero_cnt<<<(NN * RR) / T, T>>>();
    k_count<<<(EE + T - 1) / T, T>>>(ei, et);
    k_inv<<<(NN * RR) / T, T>>>();

    // ---- layer 1 ----
    k_wsplit<<<(KT * DD) / T, T>>>(W1, root1);
    k_gemm<<<gemmGrid, T, GEMM_SMEM>>>();
    k_init_out<<<(NN * 32) / T, T>>>(b1);
    k_scatter<<<(EE * 32) / T, T>>>(ei, et);
    k_act_relu<<<(NN * 32) / T, T>>>();

    // ---- layer 2 ----
    k_wsplit<<<(KT * DD) / T, T>>>(W2, root2);
    k_gemm<<<gemmGrid, T, GEMM_SMEM>>>();
    k_init_out<<<(NN * 32) / T, T>>>(b2);
    k_scatter<<<(EE * 32) / T, T>>>(ei, et);
    k_sigmoid<<<(NN * 32) / T, T>>>(out);
}

// round 4
// speedup vs baseline: 1.7870x; 1.1705x over previous
#include <cuda_runtime.h>
#include <cuda_bf16.h>
#include <math.h>
#include <stdint.h>

// Problem constants
#define NN 100000      // nodes
#define EE 500000      // edges
#define RR 8           // relations
#define DD 128         // hidden
#define KT 1152        // Wt rows: R*D (relations) + D (root)
#define NBLK 782       // ceil(NN/128)
#define NB (NBLK * RR) // edge bins: (src block, relation)

// -------- scratch (device globals; no allocation allowed) --------
__device__ __nv_bfloat16 g_xhi[(size_t)NN * DD];
__device__ __nv_bfloat16 g_xlo[(size_t)NN * DD];
__device__ __nv_bfloat16 g_wthi[(size_t)KT * DD];
__device__ __nv_bfloat16 g_wtlo[(size_t)KT * DD];
__device__ float g_out[(size_t)NN * DD];
__device__ float g_inv[(size_t)NN * RR];
__device__ int   g_cnt[(size_t)NN * RR];
__device__ int   g_bins[NB];
__device__ int   g_ptr[NB + 1];
__device__ int   g_cur[NB];
__device__ int   g_es[EE];      // sorted edges: src
__device__ int   g_ed[EE];      // sorted edges: dst
__device__ float g_einv[EE];    // sorted edges: 1/cnt(dst,rel)

// ---------------- helpers ----------------
__device__ __forceinline__ uint32_t saddr(const void* p) {
    return (uint32_t)__cvta_generic_to_shared(p);
}
__device__ __forceinline__ void ldsm_x4(uint32_t* r, uint32_t addr) {
    asm volatile("ldmatrix.sync.aligned.m8n8.x4.shared.b16 {%0,%1,%2,%3}, [%4];"
                 : "=r"(r[0]), "=r"(r[1]), "=r"(r[2]), "=r"(r[3]) : "r"(addr));
}
__device__ __forceinline__ void mma_bf16(float* c, const uint32_t* a, const uint32_t* b) {
    asm volatile("mma.sync.aligned.m16n8k16.row.col.f32.bf16.bf16.f32 "
                 "{%0,%1,%2,%3}, {%4,%5,%6,%7}, {%8,%9}, {%0,%1,%2,%3};"
                 : "+f"(c[0]), "+f"(c[1]), "+f"(c[2]), "+f"(c[3])
                 : "r"(a[0]), "r"(a[1]), "r"(a[2]), "r"(a[3]), "r"(b[0]), "r"(b[1]));
}
__device__ __forceinline__ void split2(float v, __nv_bfloat16& h, __nv_bfloat16& l) {
    h = __float2bfloat16(v);
    l = __float2bfloat16(v - __bfloat162float(h));
}
__device__ __forceinline__ void red_add4(float* p, float4 v) {
    asm volatile("red.global.add.v4.f32 [%0], {%1, %2, %3, %4};"
                 :: "l"(p), "f"(v.x), "f"(v.y), "f"(v.z), "f"(v.w) : "memory");
}

// ---------------- prep kernels ----------------
__global__ void k_gather_split(const int* __restrict__ ids, const float* __restrict__ emb) {
    int t = blockIdx.x * blockDim.x + threadIdx.x;   // NN*32 threads
    int n = t >> 5, l4 = (t & 31) * 4;
    if (n >= NN) return;
    float4 v = *((const float4*)(emb + (size_t)ids[n] * DD + l4));
    __nv_bfloat16 h0, h1, h2, h3, l0, l1, l2, l3;
    split2(v.x, h0, l0); split2(v.y, h1, l1); split2(v.z, h2, l2); split2(v.w, h3, l3);
    __nv_bfloat162* ph = (__nv_bfloat162*)(g_xhi + (size_t)n * DD + l4);
    __nv_bfloat162* pl = (__nv_bfloat162*)(g_xlo + (size_t)n * DD + l4);
    ph[0] = __nv_bfloat162{h0, h1}; ph[1] = __nv_bfloat162{h2, h3};
    pl[0] = __nv_bfloat162{l0, l1}; pl[1] = __nv_bfloat162{l2, l3};
}

// Wt[c, d]: c<1024 -> W[r=c/128][d][f=c%128]; c>=1024 -> root[d][c-1024]
__global__ void k_wsplit(const float* __restrict__ W, const float* __restrict__ rootM) {
    int t = blockIdx.x * blockDim.x + threadIdx.x;
    if (t >= KT * DD) return;
    int c = t >> 7, d = t & 127;
    float v;
    if (c < RR * DD) {
        int r = c >> 7, f = c & 127;
        v = W[((size_t)r * DD + d) * DD + f];
    } else {
        v = rootM[(size_t)d * DD + (c - RR * DD)];
    }
    __nv_bfloat16 h, l; split2(v, h, l);
    g_wthi[t] = h; g_wtlo[t] = l;
}

__global__ void k_zero_cnt() {
    int t = blockIdx.x * blockDim.x + threadIdx.x;
    if (t < NN * RR) g_cnt[t] = 0;
}
__global__ void k_count(const int* __restrict__ ei, const int* __restrict__ et) {
    int e = blockIdx.x * blockDim.x + threadIdx.x;
    if (e < EE) atomicAdd(&g_cnt[ei[EE + e] * RR + et[e]], 1);
}
__global__ void k_inv() {
    int t = blockIdx.x * blockDim.x + threadIdx.x;
    if (t < NN * RR) {
        int c = g_cnt[t];
        g_inv[t] = c > 0 ? 1.0f / (float)c : 0.0f;
    }
}

// ---- edge counting sort by (src_block, relation) ----
__global__ void k_zero_bins() {
    int t = blockIdx.x * blockDim.x + threadIdx.x;
    if (t < NB) g_bins[t] = 0;
}
__global__ void k_ehist(const int* __restrict__ ei, const int* __restrict__ et) {
    int e = blockIdx.x * blockDim.x + threadIdx.x;
    if (e < EE) {
        int bid = (ei[e] >> 7) * RR + et[e];
        atomicAdd(&g_bins[bid], 1);
    }
}
// single-block exclusive scan of g_bins -> g_ptr, g_cur (1024 threads)
__global__ void k_scan() {
    __shared__ int wsum[32];
    const int tid = threadIdx.x;
    const int per = (NB + 1023) / 1024;   // 7
    int base = tid * per;
    int loc[8]; int s = 0;
    for (int i = 0; i < per; i++) {
        int idx = base + i;
        int v = (idx < NB) ? g_bins[idx] : 0;
        loc[i] = s; s += v;
    }
    int lane = tid & 31, wid = tid >> 5;
    int x = s;
    for (int d = 1; d < 32; d <<= 1) {
        int y = __shfl_up_sync(0xffffffffu, x, d);
        if (lane >= d) x += y;
    }
    if (lane == 31) wsum[wid] = x;
    __syncthreads();
    if (wid == 0) {
        int y = wsum[lane];
        for (int d = 1; d < 32; d <<= 1) {
            int z = __shfl_up_sync(0xffffffffu, y, d);
            if (lane >= d) y += z;
        }
        wsum[lane] = y;
    }
    __syncthreads();
    int excl = x - s + (wid > 0 ? wsum[wid - 1] : 0);
    for (int i = 0; i < per; i++) {
        int idx = base + i;
        if (idx < NB) { int p = excl + loc[i]; g_ptr[idx] = p; g_cur[idx] = p; }
    }
    if (tid == 1023) g_ptr[NB] = excl + s;
}
__global__ void k_eperm(const int* __restrict__ ei, const int* __restrict__ et) {
    int e = blockIdx.x * blockDim.x + threadIdx.x;
    if (e >= EE) return;
    int src = ei[e], dst = ei[EE + e], r = et[e];
    int bid = (src >> 7) * RR + r;
    int pos = atomicAdd(&g_cur[bid], 1);
    g_es[pos] = src;
    g_ed[pos] = dst;
    g_einv[pos] = g_inv[dst * RR + r];
}

// ---------------- fused GEMM + scatter ----------------
// Per CTA (one per 128-row block): load x hi/lo tile once; loop 9 chunks of Wt.
// chunk c<8 (relation c): h-chunk -> smem, scatter pre-sorted edges of (block, c)
// via red.add to g_out (pre-zeroed). chunk 8 (root): red.add h rows to g_out.
#define PADK 136
#define GSM_AH 0
#define GSM_AL 34816
#define GSM_BH 69632
#define GSM_BL 104448
#define GSM_H  139264
#define GSM_TOTAL (GSM_H + 65536)   // 204800 bytes

__global__ __launch_bounds__(256, 1)
void k_gemm_fused() {
    extern __shared__ char sm[];
    __nv_bfloat16* Ah = (__nv_bfloat16*)(sm + GSM_AH);
    __nv_bfloat16* Al = (__nv_bfloat16*)(sm + GSM_AL);
    __nv_bfloat16* Bh = (__nv_bfloat16*)(sm + GSM_BH);
    __nv_bfloat16* Bl = (__nv_bfloat16*)(sm + GSM_BL);
    float*         hsm = (float*)(sm + GSM_H);

    const int tid  = threadIdx.x;
    const int lane = tid & 31, warp = tid >> 5;
    const int row0 = blockIdx.x * 128;

    // ---- load A (x hi/lo) once ----
    for (int v = tid; v < 2048; v += 256) {
        int r = v >> 4, c8 = (v & 15) << 3;
        int gr = row0 + r;
        uint4 h = make_uint4(0, 0, 0, 0), l = make_uint4(0, 0, 0, 0);
        if (gr < NN) {
            h = *(const uint4*)(g_xhi + (size_t)gr * DD + c8);
            l = *(const uint4*)(g_xlo + (size_t)gr * DD + c8);
        }
        *(uint4*)(Ah + r * PADK + c8) = h;
        *(uint4*)(Al + r * PADK + c8) = l;
    }

    const int wm = warp & 3;        // M: 4 warps * 32 rows
    const int wn = warp >> 2;       // N: 2 warps * 64 cols
    const int a_row  = wm * 32 + (lane & 15);
    const int a_koff = (lane >> 4) * 8;
    const int b_nrow = wn * 64 + (lane & 7) + ((lane >> 3) & 1) * 8;
    const int b_koff = (lane >> 4) * 8;

    for (int nc = 0; nc < 9; nc++) {
        __syncthreads();   // A ready (it0) / prev scatter done reading hsm

        // ---- load B chunk: Wt rows [nc*128, nc*128+128) ----
        for (int v = tid; v < 2048; v += 256) {
            int r = v >> 4, c8 = (v & 15) << 3;
            const size_t gofs = (size_t)(nc * 128 + r) * DD + c8;
            *(uint4*)(Bh + r * PADK + c8) = *(const uint4*)(g_wthi + gofs);
            *(uint4*)(Bl + r * PADK + c8) = *(const uint4*)(g_wtlo + gofs);
        }
        __syncthreads();

        float acc[2][8][4];
#pragma unroll
        for (int i = 0; i < 2; i++)
#pragma unroll
            for (int j = 0; j < 8; j++)
#pragma unroll
                for (int k = 0; k < 4; k++) acc[i][j][k] = 0.f;

#pragma unroll
        for (int ks = 0; ks < 8; ks++) {
            const int k0 = ks * 16;
            uint32_t ah[2][4], al[2][4];
#pragma unroll
            for (int mf = 0; mf < 2; mf++) {
                ldsm_x4(ah[mf], saddr(Ah + (a_row + mf * 16) * PADK + k0 + a_koff));
                ldsm_x4(al[mf], saddr(Al + (a_row + mf * 16) * PADK + k0 + a_koff));
            }
#pragma unroll
            for (int np = 0; np < 4; np++) {
                uint32_t bh[4], bl[4];
                ldsm_x4(bh, saddr(Bh + (b_nrow + np * 16) * PADK + k0 + b_koff));
                ldsm_x4(bl, saddr(Bl + (b_nrow + np * 16) * PADK + k0 + b_koff));
#pragma unroll
                for (int sub = 0; sub < 2; sub++) {
                    uint32_t bfh[2] = { bh[sub], bh[sub + 2] };
                    uint32_t bfl[2] = { bl[sub], bl[sub + 2] };
#pragma unroll
                    for (int mf = 0; mf < 2; mf++) {
                        float* c = acc[mf][np * 2 + sub];
                        mma_bf16(c, ah[mf], bfh);   // hi*hi
                        mma_bf16(c, ah[mf], bfl);   // hi*lo
                        mma_bf16(c, al[mf], bfh);   // lo*hi
                    }
                }
            }
        }

        // ---- store h chunk to smem ----
#pragma unroll
        for (int mf = 0; mf < 2; mf++) {
#pragma unroll
            for (int nf = 0; nf < 8; nf++) {
                int r = wm * 32 + mf * 16 + (lane >> 2);
                int c = wn * 64 + nf * 8 + (lane & 3) * 2;
                float* cc = acc[mf][nf];
                *(float2*)(hsm + r * 128 + c)       = make_float2(cc[0], cc[1]);
                *(float2*)(hsm + (r + 8) * 128 + c) = make_float2(cc[2], cc[3]);
            }
        }
        __syncthreads();

        if (nc < 8) {
            // ---- scatter edges of (block, relation nc) ----
            int bid = blockIdx.x * RR + nc;
            int s = g_ptr[bid], e2 = g_ptr[bid + 1];
            for (int i = s + warp; i < e2; i += 8) {
                int   ls  = g_es[i] & 127;
                int   dst = g_ed[i];
                float inv = g_einv[i];
                float4 v = *(const float4*)(hsm + ls * 128 + lane * 4);
                v.x *= inv; v.y *= inv; v.z *= inv; v.w *= inv;
                red_add4(g_out + (size_t)dst * DD + lane * 4, v);
            }
        } else {
            // ---- root chunk: add h rows to own nodes ----
            for (int rr = 0; rr < 16; rr++) {
                int r = warp * 16 + rr;
                int g = row0 + r;
                if (g < NN) {
                    float4 v = *(const float4*)(hsm + r * 128 + lane * 4);
                    red_add4(g_out + (size_t)g * DD + lane * 4, v);
                }
            }
        }
    }
}

// ---------------- activations (bias folded in) ----------------
__global__ void k_act_relu(const float* __restrict__ bias) {
    int t = blockIdx.x * blockDim.x + threadIdx.x;
    if (t >= NN * 32) return;
    float4 v = *(const float4*)(g_out + (size_t)t * 4);
    float4 b = __ldg((const float4*)(bias + (t & 31) * 4));
    v.x = fmaxf(v.x + b.x, 0.f); v.y = fmaxf(v.y + b.y, 0.f);
    v.z = fmaxf(v.z + b.z, 0.f); v.w = fmaxf(v.w + b.w, 0.f);
    __nv_bfloat16 h0, h1, h2, h3, l0, l1, l2, l3;
    split2(v.x, h0, l0); split2(v.y, h1, l1); split2(v.z, h2, l2); split2(v.w, h3, l3);
    __nv_bfloat162* ph = (__nv_bfloat162*)(g_xhi + (size_t)t * 4);
    __nv_bfloat162* pl = (__nv_bfloat162*)(g_xlo + (size_t)t * 4);
    ph[0] = __nv_bfloat162{h0, h1}; ph[1] = __nv_bfloat162{h2, h3};
    pl[0] = __nv_bfloat162{l0, l1}; pl[1] = __nv_bfloat162{l2, l3};
}

__global__ void k_sigmoid(const float* __restrict__ bias, float* __restrict__ outp) {
    int t = blockIdx.x * blockDim.x + threadIdx.x;
    if (t >= NN * 32) return;
    float4 v = *(const float4*)(g_out + (size_t)t * 4);
    float4 b = __ldg((const float4*)(bias + (t & 31) * 4));
    v.x = 1.0f / (1.0f + __expf(-(v.x + b.x)));
    v.y = 1.0f / (1.0f + __expf(-(v.y + b.y)));
    v.z = 1.0f / (1.0f + __expf(-(v.z + b.z)));
    v.w = 1.0f / (1.0f + __expf(-(v.w + b.w)));
    *(float4*)(outp + (size_t)t * 4) = v;
}

// ---------------- launch ----------------
extern "C" void kernel_launch(void* const* d_in, const int* in_sizes, int n_in,
                              void* d_out, int out_size) {
    const int*   x_ids = (const int*)  d_in[0];
    const int*   ei    = (const int*)  d_in[1];   // [2, E]: src row then dst row
    const int*   et    = (const int*)  d_in[2];
    const float* emb   = (const float*)d_in[3];
    const float* W1    = (const float*)d_in[4];
    const float* root1 = (const float*)d_in[5];
    const float* b1    = (const float*)d_in[6];
    const float* W2    = (const float*)d_in[7];
    const float* root2 = (const float*)d_in[8];
    const float* b2    = (const float*)d_in[9];
    float*       out   = (float*)d_out;
    (void)in_sizes; (void)n_in; (void)out_size;

    cudaFuncSetAttribute(k_gemm_fused, cudaFuncAttributeMaxDynamicSharedMemorySize, GSM_TOTAL);

    float* gout_ptr = nullptr;
    cudaGetSymbolAddress((void**)&gout_ptr, g_out);

    const int T = 256;

    // ---- prep ----
    k_gather_split<<<(NN * 32) / T, T>>>(x_ids, emb);
    k_zero_cnt<<<(NN * RR) / T, T>>>();
    k_count<<<(EE + T - 1) / T, T>>>(ei, et);
    k_inv<<<(NN * RR) / T, T>>>();
    k_zero_bins<<<(NB + T - 1) / T, T>>>();
    k_ehist<<<(EE + T - 1) / T, T>>>(ei, et);
    k_scan<<<1, 1024>>>();
    k_eperm<<<(EE + T - 1) / T, T>>>(ei, et);

    // ---- layer 1 ----
    cudaMemsetAsync(gout_ptr, 0, (size_t)NN * DD * sizeof(float));
    k_wsplit<<<(KT * DD) / T, T>>>(W1, root1);
    k_gemm_fused<<<NBLK, 256, GSM_TOTAL>>>();
    k_act_relu<<<(NN * 32) / T, T>>>(b1);

    // ---- layer 2 ----
    cudaMemsetAsync(gout_ptr, 0, (size_t)NN * DD * sizeof(float));
    k_wsplit<<<(KT * DD) / T, T>>>(W2, root2);
    k_gemm_fused<<<NBLK, 256, GSM_TOTAL>>>();
    k_sigmoid<<<(NN * 32) / T, T>>>(b2, out);
}

// round 5
// speedup vs baseline: 1.9027x; 1.0647x over previous
#include <cuda_runtime.h>
#include <cuda_bf16.h>
#include <math.h>
#include <stdint.h>

// Problem constants
#define NN 100000      // nodes
#define EE 500000      // edges
#define RR 8           // relations
#define DD 128         // hidden
#define KT 1152        // Wt rows: R*D (relations) + D (root)
#define NPAIR (NN * RR)            // 800000 (node, rel) pairs
#define MAXBLK ((NPAIR + 8 * 127 + 127) / 128)   // 6258 max 128-row blocks after padding
#define NVROW (MAXBLK * 128)

// -------- scratch (device globals; no allocation allowed) --------
__device__ __nv_bfloat16 g_xhi[(size_t)NN * DD];
__device__ __nv_bfloat16 g_xlo[(size_t)NN * DD];
__device__ __nv_bfloat16 g_wthi[(size_t)KT * DD];
__device__ __nv_bfloat16 g_wtlo[(size_t)KT * DD];
__device__ float g_out[(size_t)NN * DD];
__device__ float g_inv[NPAIR];       // 1/indeg(dst,rel)
__device__ int   g_cnt[NPAIR];       // in-degree per (dst,rel)
__device__ int   g_scnt[NPAIR];      // out-degree per (src,rel)
__device__ int   g_pos[NPAIR];       // (src,rel) -> virtual row
__device__ int   g_vnode[NVROW];     // virtual row -> node (-1 = pad)
__device__ int   g_relnz[RR];
__device__ int   g_fill[RR];
__device__ int   g_base[RR + 1];
__device__ int   g_nblk;             // active blocks
__device__ int   g_blockrel[MAXBLK];
__device__ int   g_bins[MAXBLK];
__device__ int   g_ptr[MAXBLK + 1];
__device__ int   g_cur[MAXBLK];
__device__ int   g_els[EE];          // sorted edges: local src row (pos & 127)
__device__ int   g_ed[EE];           // sorted edges: dst
__device__ float g_einv[EE];         // sorted edges: 1/cnt(dst,rel)

// ---------------- helpers ----------------
__device__ __forceinline__ uint32_t saddr(const void* p) {
    return (uint32_t)__cvta_generic_to_shared(p);
}
__device__ __forceinline__ void ldsm_x4(uint32_t* r, uint32_t addr) {
    asm volatile("ldmatrix.sync.aligned.m8n8.x4.shared.b16 {%0,%1,%2,%3}, [%4];"
                 : "=r"(r[0]), "=r"(r[1]), "=r"(r[2]), "=r"(r[3]) : "r"(addr));
}
__device__ __forceinline__ void mma_bf16(float* c, const uint32_t* a, const uint32_t* b) {
    asm volatile("mma.sync.aligned.m16n8k16.row.col.f32.bf16.bf16.f32 "
                 "{%0,%1,%2,%3}, {%4,%5,%6,%7}, {%8,%9}, {%0,%1,%2,%3};"
                 : "+f"(c[0]), "+f"(c[1]), "+f"(c[2]), "+f"(c[3])
                 : "r"(a[0]), "r"(a[1]), "r"(a[2]), "r"(a[3]), "r"(b[0]), "r"(b[1]));
}
__device__ __forceinline__ void split2(float v, __nv_bfloat16& h, __nv_bfloat16& l) {
    h = __float2bfloat16(v);
    l = __float2bfloat16(v - __bfloat162float(h));
}
__device__ __forceinline__ void red_add4(float* p, float4 v) {
    asm volatile("red.global.add.v4.f32 [%0], {%1, %2, %3, %4};"
                 :: "l"(p), "f"(v.x), "f"(v.y), "f"(v.z), "f"(v.w) : "memory");
}

// ---------------- prep kernels ----------------
__global__ void k_gather_split(const int* __restrict__ ids, const float* __restrict__ emb) {
    int t = blockIdx.x * blockDim.x + threadIdx.x;   // NN*32 threads
    int n = t >> 5, l4 = (t & 31) * 4;
    if (n >= NN) return;
    float4 v = *((const float4*)(emb + (size_t)ids[n] * DD + l4));
    __nv_bfloat16 h0, h1, h2, h3, l0, l1, l2, l3;
    split2(v.x, h0, l0); split2(v.y, h1, l1); split2(v.z, h2, l2); split2(v.w, h3, l3);
    __nv_bfloat162* ph = (__nv_bfloat162*)(g_xhi + (size_t)n * DD + l4);
    __nv_bfloat162* pl = (__nv_bfloat162*)(g_xlo + (size_t)n * DD + l4);
    ph[0] = __nv_bfloat162{h0, h1}; ph[1] = __nv_bfloat162{h2, h3};
    pl[0] = __nv_bfloat162{l0, l1}; pl[1] = __nv_bfloat162{l2, l3};
}

// Wt[c, d]: c<1024 -> W[r=c/128][d][f=c%128]; c>=1024 -> root[d][c-1024]
__global__ void k_wsplit(const float* __restrict__ W, const float* __restrict__ rootM) {
    int t = blockIdx.x * blockDim.x + threadIdx.x;
    if (t >= KT * DD) return;
    int c = t >> 7, d = t & 127;
    float v;
    if (c < RR * DD) {
        int r = c >> 7, f = c & 127;
        v = W[((size_t)r * DD + d) * DD + f];
    } else {
        v = rootM[(size_t)d * DD + (c - RR * DD)];
    }
    __nv_bfloat16 h, l; split2(v, h, l);
    g_wthi[t] = h; g_wtlo[t] = l;
}

__global__ void k_zero_prep() {
    int t = blockIdx.x * blockDim.x + threadIdx.x;
    if (t < NPAIR) { g_cnt[t] = 0; g_scnt[t] = 0; }
    if (t < RR) { g_relnz[t] = 0; g_fill[t] = 0; }
    if (t < MAXBLK) g_bins[t] = 0;
    if (t < NVROW) g_vnode[t] = -1;   // NVROW > NPAIR; guard:
}
__global__ void k_hist2(const int* __restrict__ ei, const int* __restrict__ et) {
    int e = blockIdx.x * blockDim.x + threadIdx.x;
    if (e >= EE) return;
    int src = ei[e], dst = ei[EE + e], r = et[e];
    atomicAdd(&g_cnt[dst * RR + r], 1);
    atomicAdd(&g_scnt[src * RR + r], 1);
}
__global__ void k_inv_relnz() {
    int t = blockIdx.x * blockDim.x + threadIdx.x;
    if (t >= NPAIR) return;
    int c = g_cnt[t];
    g_inv[t] = c > 0 ? 1.0f / (float)c : 0.0f;
    if (g_scnt[t] > 0) atomicAdd(&g_relnz[t & (RR - 1)], 1);
}
// base[r]: 128-padded prefix sums of per-relation live pair counts
__global__ void k_bases() {
    if (threadIdx.x == 0) {
        int b = 0;
        g_base[0] = 0;
        for (int r = 0; r < RR; r++) {
            b += (g_relnz[r] + 127) & ~127;
            g_base[r + 1] = b;
        }
        g_nblk = b >> 7;
    }
}
__global__ void k_blockrel() {
    int b = blockIdx.x * blockDim.x + threadIdx.x;
    if (b >= MAXBLK) return;
    int row = b * 128, rel = 0;
    for (int r = 0; r < RR; r++)
        if (row >= g_base[r] && row < g_base[r + 1]) rel = r;
    g_blockrel[b] = rel;
}
__global__ void k_compact() {
    int t = blockIdx.x * blockDim.x + threadIdx.x;
    if (t >= NPAIR) return;
    if (g_scnt[t] > 0) {
        int node = t >> 3;              // RR == 8
        int rel  = t & 7;
        int pos = g_base[rel] + atomicAdd(&g_fill[rel], 1);
        g_vnode[pos] = node;
        g_pos[t] = pos;
    }
}
__global__ void k_ehist(const int* __restrict__ ei, const int* __restrict__ et) {
    int e = blockIdx.x * blockDim.x + threadIdx.x;
    if (e >= EE) return;
    int bid = g_pos[ei[e] * RR + et[e]] >> 7;
    atomicAdd(&g_bins[bid], 1);
}
// single-block exclusive scan over MAXBLK bins
__global__ void k_scan() {
    __shared__ int wsum[32];
    const int tid = threadIdx.x;
    const int per = (MAXBLK + 1023) / 1024;   // 7
    int base = tid * per;
    int loc[8]; int s = 0;
    for (int i = 0; i < per; i++) {
        int idx = base + i;
        int v = (idx < MAXBLK) ? g_bins[idx] : 0;
        loc[i] = s; s += v;
    }
    int lane = tid & 31, wid = tid >> 5;
    int x = s;
    for (int d = 1; d < 32; d <<= 1) {
        int y = __shfl_up_sync(0xffffffffu, x, d);
        if (lane >= d) x += y;
    }
    if (lane == 31) wsum[wid] = x;
    __syncthreads();
    if (wid == 0) {
        int y = wsum[lane];
        for (int d = 1; d < 32; d <<= 1) {
            int z = __shfl_up_sync(0xffffffffu, y, d);
            if (lane >= d) y += z;
        }
        wsum[lane] = y;
    }
    __syncthreads();
    int excl = x - s + (wid > 0 ? wsum[wid - 1] : 0);
    for (int i = 0; i < per; i++) {
        int idx = base + i;
        if (idx < MAXBLK) { int p = excl + loc[i]; g_ptr[idx] = p; g_cur[idx] = p; }
    }
    if (tid == 1023) g_ptr[MAXBLK] = excl + s;
}
__global__ void k_eperm(const int* __restrict__ ei, const int* __restrict__ et) {
    int e = blockIdx.x * blockDim.x + threadIdx.x;
    if (e >= EE) return;
    int src = ei[e], dst = ei[EE + e], r = et[e];
    int pos = g_pos[src * RR + r];
    int i = atomicAdd(&g_cur[pos >> 7], 1);
    g_els[i]  = pos & 127;
    g_ed[i]   = dst;
    g_einv[i] = g_inv[dst * RR + r];
}

// ---------------- GEMM kernels ----------------
#define PADK 136
#define GSM_AH 0
#define GSM_AL 34816
#define GSM_BH 69632
#define GSM_BL 104448
#define GSM_H  139264
#define GSM_REL_TOTAL  (GSM_H + 65536)   // 204800
#define GSM_ROOT_TOTAL GSM_H             // 139264

// shared MMA core: computes 128x128 tile, acc in registers
#define MMA_CORE(Ah, Al, Bh, Bl, acc)                                              \
    {                                                                              \
        _Pragma("unroll")                                                          \
        for (int ks = 0; ks < 8; ks++) {                                           \
            const int k0 = ks * 16;                                                \
            uint32_t ah[2][4], al[2][4];                                           \
            _Pragma("unroll")                                                      \
            for (int mf = 0; mf < 2; mf++) {                                       \
                ldsm_x4(ah[mf], saddr(Ah + (a_row + mf * 16) * PADK + k0 + a_koff));\
                ldsm_x4(al[mf], saddr(Al + (a_row + mf * 16) * PADK + k0 + a_koff));\
            }                                                                      \
            _Pragma("unroll")                                                      \
            for (int np = 0; np < 4; np++) {                                       \
                uint32_t bh[4], bl[4];                                             \
                ldsm_x4(bh, saddr(Bh + (b_nrow + np * 16) * PADK + k0 + b_koff));  \
                ldsm_x4(bl, saddr(Bl + (b_nrow + np * 16) * PADK + k0 + b_koff));  \
                _Pragma("unroll")                                                  \
                for (int sub = 0; sub < 2; sub++) {                                \
                    uint32_t bfh[2] = { bh[sub], bh[sub + 2] };                    \
                    uint32_t bfl[2] = { bl[sub], bl[sub + 2] };                    \
                    _Pragma("unroll")                                              \
                    for (int mf = 0; mf < 2; mf++) {                               \
                        float* c = acc[mf][np * 2 + sub];                          \
                        mma_bf16(c, ah[mf], bfh);                                  \
                        mma_bf16(c, ah[mf], bfl);                                  \
                        mma_bf16(c, al[mf], bfh);                                  \
                    }                                                              \
                }                                                                  \
            }                                                                      \
        }                                                                          \
    }

// root GEMM: g_out[n,:] = x[n,:] @ root  (plain store; scatter adds later)
__global__ __launch_bounds__(256, 1)
void k_gemm_root() {
    extern __shared__ char sm[];
    __nv_bfloat16* Ah = (__nv_bfloat16*)(sm + GSM_AH);
    __nv_bfloat16* Al = (__nv_bfloat16*)(sm + GSM_AL);
    __nv_bfloat16* Bh = (__nv_bfloat16*)(sm + GSM_BH);
    __nv_bfloat16* Bl = (__nv_bfloat16*)(sm + GSM_BL);

    const int tid  = threadIdx.x;
    const int lane = tid & 31, warp = tid >> 5;
    const int row0 = blockIdx.x * 128;

    for (int v = tid; v < 2048; v += 256) {
        int r = v >> 4, c8 = (v & 15) << 3;
        int gr = row0 + r;
        uint4 h = make_uint4(0, 0, 0, 0), l = make_uint4(0, 0, 0, 0);
        if (gr < NN) {
            h = *(const uint4*)(g_xhi + (size_t)gr * DD + c8);
            l = *(const uint4*)(g_xlo + (size_t)gr * DD + c8);
        }
        *(uint4*)(Ah + r * PADK + c8) = h;
        *(uint4*)(Al + r * PADK + c8) = l;
        const size_t gofs = (size_t)(RR * DD + r) * DD + c8;   // root rows of Wt
        *(uint4*)(Bh + r * PADK + c8) = *(const uint4*)(g_wthi + gofs);
        *(uint4*)(Bl + r * PADK + c8) = *(const uint4*)(g_wtlo + gofs);
    }
    __syncthreads();

    const int wm = warp & 3, wn = warp >> 2;
    const int a_row  = wm * 32 + (lane & 15);
    const int a_koff = (lane >> 4) * 8;
    const int b_nrow = wn * 64 + (lane & 7) + ((lane >> 3) & 1) * 8;
    const int b_koff = (lane >> 4) * 8;

    float acc[2][8][4];
#pragma unroll
    for (int i = 0; i < 2; i++)
#pragma unroll
        for (int j = 0; j < 8; j++)
#pragma unroll
            for (int k = 0; k < 4; k++) acc[i][j][k] = 0.f;

    MMA_CORE(Ah, Al, Bh, Bl, acc)

#pragma unroll
    for (int mf = 0; mf < 2; mf++) {
#pragma unroll
        for (int nf = 0; nf < 8; nf++) {
            int r = row0 + wm * 32 + mf * 16 + (lane >> 2);
            int c = wn * 64 + nf * 8 + (lane & 3) * 2;
            float* cc = acc[mf][nf];
            if (r < NN)
                *(float2*)(g_out + (size_t)r * DD + c) = make_float2(cc[0], cc[1]);
            if (r + 8 < NN)
                *(float2*)(g_out + (size_t)(r + 8) * DD + c) = make_float2(cc[2], cc[3]);
        }
    }
}

// relation GEMM + fused scatter over compacted virtual rows
__global__ __launch_bounds__(256, 1)
void k_gemm_rel() {
    if ((int)blockIdx.x >= g_nblk) return;
    extern __shared__ char sm[];
    __nv_bfloat16* Ah = (__nv_bfloat16*)(sm + GSM_AH);
    __nv_bfloat16* Al = (__nv_bfloat16*)(sm + GSM_AL);
    __nv_bfloat16* Bh = (__nv_bfloat16*)(sm + GSM_BH);
    __nv_bfloat16* Bl = (__nv_bfloat16*)(sm + GSM_BL);
    float*         hsm = (float*)(sm + GSM_H);

    const int tid  = threadIdx.x;
    const int lane = tid & 31, warp = tid >> 5;
    const int row0 = blockIdx.x * 128;
    const int rel  = g_blockrel[blockIdx.x];

    // A gather via virtual-row table; B = this relation's 128 Wt rows
    for (int v = tid; v < 2048; v += 256) {
        int r = v >> 4, c8 = (v & 15) << 3;
        int node = g_vnode[row0 + r];
        uint4 h = make_uint4(0, 0, 0, 0), l = make_uint4(0, 0, 0, 0);
        if (node >= 0) {
            h = *(const uint4*)(g_xhi + (size_t)node * DD + c8);
            l = *(const uint4*)(g_xlo + (size_t)node * DD + c8);
        }
        *(uint4*)(Ah + r * PADK + c8) = h;
        *(uint4*)(Al + r * PADK + c8) = l;
        const size_t gofs = (size_t)(rel * DD + r) * DD + c8;
        *(uint4*)(Bh + r * PADK + c8) = *(const uint4*)(g_wthi + gofs);
        *(uint4*)(Bl + r * PADK + c8) = *(const uint4*)(g_wtlo + gofs);
    }
    __syncthreads();

    const int wm = warp & 3, wn = warp >> 2;
    const int a_row  = wm * 32 + (lane & 15);
    const int a_koff = (lane >> 4) * 8;
    const int b_nrow = wn * 64 + (lane & 7) + ((lane >> 3) & 1) * 8;
    const int b_koff = (lane >> 4) * 8;

    float acc[2][8][4];
#pragma unroll
    for (int i = 0; i < 2; i++)
#pragma unroll
        for (int j = 0; j < 8; j++)
#pragma unroll
            for (int k = 0; k < 4; k++) acc[i][j][k] = 0.f;

    MMA_CORE(Ah, Al, Bh, Bl, acc)

    // h chunk -> smem
#pragma unroll
    for (int mf = 0; mf < 2; mf++) {
#pragma unroll
        for (int nf = 0; nf < 8; nf++) {
            int r = wm * 32 + mf * 16 + (lane >> 2);
            int c = wn * 64 + nf * 8 + (lane & 3) * 2;
            float* cc = acc[mf][nf];
            *(float2*)(hsm + r * 128 + c)       = make_float2(cc[0], cc[1]);
            *(float2*)(hsm + (r + 8) * 128 + c) = make_float2(cc[2], cc[3]);
        }
    }
    __syncthreads();

    // scatter this block's edges
    int s = g_ptr[blockIdx.x], e2 = g_ptr[blockIdx.x + 1];
    for (int i = s + warp; i < e2; i += 8) {
        int   ls  = g_els[i];
        int   dst = g_ed[i];
        float inv = g_einv[i];
        float4 v = *(const float4*)(hsm + ls * 128 + lane * 4);
        v.x *= inv; v.y *= inv; v.z *= inv; v.w *= inv;
        red_add4(g_out + (size_t)dst * DD + lane * 4, v);
    }
}

// ---------------- activations (bias folded in) ----------------
__global__ void k_act_relu(const float* __restrict__ bias) {
    int t = blockIdx.x * blockDim.x + threadIdx.x;
    if (t >= NN * 32) return;
    float4 v = *(const float4*)(g_out + (size_t)t * 4);
    float4 b = __ldg((const float4*)(bias + (t & 31) * 4));
    v.x = fmaxf(v.x + b.x, 0.f); v.y = fmaxf(v.y + b.y, 0.f);
    v.z = fmaxf(v.z + b.z, 0.f); v.w = fmaxf(v.w + b.w, 0.f);
    __nv_bfloat16 h0, h1, h2, h3, l0, l1, l2, l3;
    split2(v.x, h0, l0); split2(v.y, h1, l1); split2(v.z, h2, l2); split2(v.w, h3, l3);
    __nv_bfloat162* ph = (__nv_bfloat162*)(g_xhi + (size_t)t * 4);
    __nv_bfloat162* pl = (__nv_bfloat162*)(g_xlo + (size_t)t * 4);
    ph[0] = __nv_bfloat162{h0, h1}; ph[1] = __nv_bfloat162{h2, h3};
    pl[0] = __nv_bfloat162{l0, l1}; pl[1] = __nv_bfloat162{l2, l3};
}

__global__ void k_sigmoid(const float* __restrict__ bias, float* __restrict__ outp) {
    int t = blockIdx.x * blockDim.x + threadIdx.x;
    if (t >= NN * 32) return;
    float4 v = *(const float4*)(g_out + (size_t)t * 4);
    float4 b = __ldg((const float4*)(bias + (t & 31) * 4));
    v.x = 1.0f / (1.0f + __expf(-(v.x + b.x)));
    v.y = 1.0f / (1.0f + __expf(-(v.y + b.y)));
    v.z = 1.0f / (1.0f + __expf(-(v.z + b.z)));
    v.w = 1.0f / (1.0f + __expf(-(v.w + b.w)));
    *(float4*)(outp + (size_t)t * 4) = v;
}

// ---------------- launch ----------------
extern "C" void kernel_launch(void* const* d_in, const int* in_sizes, int n_in,
                              void* d_out, int out_size) {
    const int*   x_ids = (const int*)  d_in[0];
    const int*   ei    = (const int*)  d_in[1];   // [2, E]: src row then dst row
    const int*   et    = (const int*)  d_in[2];
    const float* emb   = (const float*)d_in[3];
    const float* W1    = (const float*)d_in[4];
    const float* root1 = (const float*)d_in[5];
    const float* b1    = (const float*)d_in[6];
    const float* W2    = (const float*)d_in[7];
    const float* root2 = (const float*)d_in[8];
    const float* b2    = (const float*)d_in[9];
    float*       out   = (float*)d_out;
    (void)in_sizes; (void)n_in; (void)out_size;

    cudaFuncSetAttribute(k_gemm_rel,  cudaFuncAttributeMaxDynamicSharedMemorySize, GSM_REL_TOTAL);
    cudaFuncSetAttribute(k_gemm_root, cudaFuncAttributeMaxDynamicSharedMemorySize, GSM_ROOT_TOTAL);

    const int T = 256;

    // ---- prep ----
    k_gather_split<<<(NN * 32) / T, T>>>(x_ids, emb);
    k_zero_prep<<<(NVROW + T - 1) / T, T>>>();
    k_hist2<<<(EE + T - 1) / T, T>>>(ei, et);
    k_inv_relnz<<<(NPAIR + T - 1) / T, T>>>();
    k_bases<<<1, 32>>>();
    k_blockrel<<<(MAXBLK + T - 1) / T, T>>>();
    k_compact<<<(NPAIR + T - 1) / T, T>>>();
    k_ehist<<<(EE + T - 1) / T, T>>>(ei, et);
    k_scan<<<1, 1024>>>();
    k_eperm<<<(EE + T - 1) / T, T>>>(ei, et);

    const int rootBlocks = (NN + 127) / 128;   // 782

    // ---- layer 1 ----
    k_wsplit<<<(KT * DD) / T, T>>>(W1, root1);
    k_gemm_root<<<rootBlocks, 256, GSM_ROOT_TOTAL>>>();
    k_gemm_rel<<<MAXBLK, 256, GSM_REL_TOTAL>>>();
    k_act_relu<<<(NN * 32) / T, T>>>(b1);

    // ---- layer 2 ----
    k_wsplit<<<(KT * DD) / T, T>>>(W2, root2);
    k_gemm_root<<<rootBlocks, 256, GSM_ROOT_TOTAL>>>();
    k_gemm_rel<<<MAXBLK, 256, GSM_REL_TOTAL>>>();
    k_sigmoid<<<(NN * 32) / T, T>>>(b2, out);
}

// round 6
// speedup vs baseline: 2.6865x; 1.4119x over previous
#include <cuda_runtime.h>
#include <cuda_bf16.h>
#include <math.h>
#include <stdint.h>

// Problem constants
#define NN 100000      // nodes
#define EE 500000      // edges
#define RR 8           // relations
#define DD 128         // hidden
#define KT 1152        // Wt rows: R*D (relations) + D (root)
#define NPAIR (NN * RR)                     // 800000 (node, rel) pairs
#define TM 64                               // GEMM tile M
#define MAXBLK ((NPAIR + RR * (TM - 1) + TM - 1) / TM)   // max 64-row blocks after padding
#define NVROW (MAXBLK * TM)

// -------- scratch (device globals; no allocation allowed) --------
__device__ __nv_bfloat16 g_xhi[(size_t)NN * DD];
__device__ __nv_bfloat16 g_xlo[(size_t)NN * DD];
__device__ __nv_bfloat16 g_wthi[2 * (size_t)KT * DD];   // both layers
__device__ __nv_bfloat16 g_wtlo[2 * (size_t)KT * DD];
__device__ float g_out[(size_t)NN * DD];
__device__ float g_inv[NPAIR];       // 1/indeg(dst,rel)
__device__ int   g_cnt[NPAIR];       // in-degree per (dst,rel)
__device__ int   g_scnt[NPAIR];      // out-degree per (src,rel)
__device__ int   g_pos[NPAIR];       // (src,rel) -> virtual row
__device__ int   g_vnode[NVROW];     // virtual row -> node (-1 = pad)
__device__ int   g_relnz[RR];
__device__ int   g_fill[RR];
__device__ int   g_base[RR + 1];
__device__ int   g_nblk;             // active blocks
__device__ int   g_blockrel[MAXBLK];
__device__ int   g_bins[MAXBLK];
__device__ int   g_ptr[MAXBLK + 1];
__device__ int   g_cur[MAXBLK];
__device__ int   g_els[EE];          // sorted edges: local src row (pos % TM)
__device__ int   g_ed[EE];           // sorted edges: dst
__device__ float g_einv[EE];         // sorted edges: 1/cnt(dst,rel)

// ---------------- helpers ----------------
__device__ __forceinline__ uint32_t saddr(const void* p) {
    return (uint32_t)__cvta_generic_to_shared(p);
}
__device__ __forceinline__ void ldsm_x4(uint32_t* r, uint32_t addr) {
    asm volatile("ldmatrix.sync.aligned.m8n8.x4.shared.b16 {%0,%1,%2,%3}, [%4];"
                 : "=r"(r[0]), "=r"(r[1]), "=r"(r[2]), "=r"(r[3]) : "r"(addr));
}
__device__ __forceinline__ void mma_bf16(float* c, const uint32_t* a, const uint32_t* b) {
    asm volatile("mma.sync.aligned.m16n8k16.row.col.f32.bf16.bf16.f32 "
                 "{%0,%1,%2,%3}, {%4,%5,%6,%7}, {%8,%9}, {%0,%1,%2,%3};"
                 : "+f"(c[0]), "+f"(c[1]), "+f"(c[2]), "+f"(c[3])
                 : "r"(a[0]), "r"(a[1]), "r"(a[2]), "r"(a[3]), "r"(b[0]), "r"(b[1]));
}
__device__ __forceinline__ void split2(float v, __nv_bfloat16& h, __nv_bfloat16& l) {
    h = __float2bfloat16(v);
    l = __float2bfloat16(v - __bfloat162float(h));
}
__device__ __forceinline__ void red_add4(float* p, float4 v) {
    asm volatile("red.global.add.v4.f32 [%0], {%1, %2, %3, %4};"
                 :: "l"(p), "f"(v.x), "f"(v.y), "f"(v.z), "f"(v.w) : "memory");
}

// ---------------- prep kernels ----------------
__global__ void k_gather_split(const int* __restrict__ ids, const float* __restrict__ emb) {
    int t = blockIdx.x * blockDim.x + threadIdx.x;   // NN*32 threads
    int n = t >> 5, l4 = (t & 31) * 4;
    if (n >= NN) return;
    float4 v = *((const float4*)(emb + (size_t)ids[n] * DD + l4));
    __nv_bfloat16 h0, h1, h2, h3, l0, l1, l2, l3;
    split2(v.x, h0, l0); split2(v.y, h1, l1); split2(v.z, h2, l2); split2(v.w, h3, l3);
    __nv_bfloat162* ph = (__nv_bfloat162*)(g_xhi + (size_t)n * DD + l4);
    __nv_bfloat162* pl = (__nv_bfloat162*)(g_xlo + (size_t)n * DD + l4);
    ph[0] = __nv_bfloat162{h0, h1}; ph[1] = __nv_bfloat162{h2, h3};
    pl[0] = __nv_bfloat162{l0, l1}; pl[1] = __nv_bfloat162{l2, l3};
}

// Wt[c, d] for layer L: c<1024 -> W[r=c/128][d][f=c%128]; c>=1024 -> root[d][c-1024]
__global__ void k_wsplit(const float* __restrict__ W, const float* __restrict__ rootM, int loff) {
    int t = blockIdx.x * blockDim.x + threadIdx.x;
    if (t >= KT * DD) return;
    int c = t >> 7, d = t & 127;
    float v;
    if (c < RR * DD) {
        int r = c >> 7, f = c & 127;
        v = W[((size_t)r * DD + d) * DD + f];
    } else {
        v = rootM[(size_t)d * DD + (c - RR * DD)];
    }
    __nv_bfloat16 h, l; split2(v, h, l);
    g_wthi[loff + t] = h; g_wtlo[loff + t] = l;
}

__global__ void k_zero_prep() {
    int t = blockIdx.x * blockDim.x + threadIdx.x;
    if (t < NPAIR) { g_cnt[t] = 0; g_scnt[t] = 0; }
    if (t < RR) { g_relnz[t] = 0; g_fill[t] = 0; }
    if (t < MAXBLK) g_bins[t] = 0;
    if (t < NVROW) g_vnode[t] = -1;
}
__global__ void k_hist2(const int* __restrict__ ei, const int* __restrict__ et) {
    int e = blockIdx.x * blockDim.x + threadIdx.x;
    if (e >= EE) return;
    int src = ei[e], dst = ei[EE + e], r = et[e];
    atomicAdd(&g_cnt[dst * RR + r], 1);
    atomicAdd(&g_scnt[src * RR + r], 1);
}
// inv + per-relation live-pair counts (block-aggregated atomics)
__global__ void k_inv_relnz() {
    __shared__ int c[RR];
    if (threadIdx.x < RR) c[threadIdx.x] = 0;
    __syncthreads();
    int t = blockIdx.x * blockDim.x + threadIdx.x;
    if (t < NPAIR) {
        int n = g_cnt[t];
        g_inv[t] = n > 0 ? 1.0f / (float)n : 0.0f;
        if (g_scnt[t] > 0) atomicAdd(&c[t & (RR - 1)], 1);
    }
    __syncthreads();
    if (threadIdx.x < RR && c[threadIdx.x] > 0) atomicAdd(&g_relnz[threadIdx.x], c[threadIdx.x]);
}
// base[r]: TM-padded prefix sums of per-relation live pair counts
__global__ void k_bases() {
    if (threadIdx.x == 0) {
        int b = 0;
        g_base[0] = 0;
        for (int r = 0; r < RR; r++) {
            b += (g_relnz[r] + TM - 1) & ~(TM - 1);
            g_base[r + 1] = b;
        }
        g_nblk = b / TM;
    }
}
__global__ void k_blockrel() {
    int b = blockIdx.x * blockDim.x + threadIdx.x;
    if (b >= MAXBLK) return;
    int row = b * TM, rel = 0;
    for (int r = 0; r < RR; r++)
        if (row >= g_base[r] && row < g_base[r + 1]) rel = r;
    g_blockrel[b] = rel;
}
__global__ void k_compact() {
    int t = blockIdx.x * blockDim.x + threadIdx.x;
    if (t >= NPAIR) return;
    if (g_scnt[t] > 0) {
        int node = t >> 3;              // RR == 8
        int rel  = t & 7;
        int pos = g_base[rel] + atomicAdd(&g_fill[rel], 1);
        g_vnode[pos] = node;
        g_pos[t] = pos;
    }
}
__global__ void k_ehist(const int* __restrict__ ei, const int* __restrict__ et) {
    int e = blockIdx.x * blockDim.x + threadIdx.x;
    if (e >= EE) return;
    int bid = g_pos[ei[e] * RR + et[e]] / TM;
    atomicAdd(&g_bins[bid], 1);
}
// single-block exclusive scan over MAXBLK bins
__global__ void k_scan() {
    __shared__ int wsum[32];
    const int tid = threadIdx.x;
    const int per = (MAXBLK + 1023) / 1024;
    int base = tid * per;
    int loc[16]; int s = 0;
    for (int i = 0; i < per; i++) {
        int idx = base + i;
        int v = (idx < MAXBLK) ? g_bins[idx] : 0;
        loc[i] = s; s += v;
    }
    int lane = tid & 31, wid = tid >> 5;
    int x = s;
    for (int d = 1; d < 32; d <<= 1) {
        int y = __shfl_up_sync(0xffffffffu, x, d);
        if (lane >= d) x += y;
    }
    if (lane == 31) wsum[wid] = x;
    __syncthreads();
    if (wid == 0) {
        int y = wsum[lane];
        for (int d = 1; d < 32; d <<= 1) {
            int z = __shfl_up_sync(0xffffffffu, y, d);
            if (lane >= d) y += z;
        }
        wsum[lane] = y;
    }
    __syncthreads();
    int excl = x - s + (wid > 0 ? wsum[wid - 1] : 0);
    for (int i = 0; i < per; i++) {
        int idx = base + i;
        if (idx < MAXBLK) { int p = excl + loc[i]; g_ptr[idx] = p; g_cur[idx] = p; }
    }
    if (tid == 1023) g_ptr[MAXBLK] = excl + s;
}
__global__ void k_eperm(const int* __restrict__ ei, const int* __restrict__ et) {
    int e = blockIdx.x * blockDim.x + threadIdx.x;
    if (e >= EE) return;
    int src = ei[e], dst = ei[EE + e], r = et[e];
    int pos = g_pos[src * RR + r];
    int i = atomicAdd(&g_cur[pos / TM], 1);
    g_els[i]  = pos % TM;
    g_ed[i]   = dst;
    g_einv[i] = g_inv[dst * RR + r];
}

// ---------------- GEMM kernels (tile 64x128, occ 2) ----------------
#define PADK 136
#define GSM_AH 0
#define GSM_AL 17408
#define GSM_BH 34816
#define GSM_BL 69632
#define GSM_TOTAL 104448     // per-CTA dynamic smem; 2 CTAs/SM

// MMA core: 64(M) x 128(N) x 128(K), warps 2(M) x 4(N), warp tile 32x32
#define MMA_CORE(Ah, Al, Bh, Bl, acc)                                              \
    {                                                                              \
        _Pragma("unroll")                                                          \
        for (int ks = 0; ks < 8; ks++) {                                           \
            const int k0 = ks * 16;                                                \
            uint32_t ah[2][4], al[2][4];                                           \
            _Pragma("unroll")                                                      \
            for (int mf = 0; mf < 2; mf++) {                                       \
                ldsm_x4(ah[mf], saddr(Ah + (a_row + mf * 16) * PADK + k0 + a_koff));\
                ldsm_x4(al[mf], saddr(Al + (a_row + mf * 16) * PADK + k0 + a_koff));\
            }                                                                      \
            _Pragma("unroll")                                                      \
            for (int np = 0; np < 2; np++) {                                       \
                uint32_t bh[4], bl[4];                                             \
                ldsm_x4(bh, saddr(Bh + (b_nrow + np * 16) * PADK + k0 + b_koff));  \
                ldsm_x4(bl, saddr(Bl + (b_nrow + np * 16) * PADK + k0 + b_koff));  \
                _Pragma("unroll")                                                  \
                for (int sub = 0; sub < 2; sub++) {                                \
                    uint32_t bfh[2] = { bh[sub], bh[sub + 2] };                    \
                    uint32_t bfl[2] = { bl[sub], bl[sub + 2] };                    \
                    _Pragma("unroll")                                              \
                    for (int mf = 0; mf < 2; mf++) {                               \
                        float* c = acc[mf][np * 2 + sub];                          \
                        mma_bf16(c, ah[mf], bfh);                                  \
                        mma_bf16(c, ah[mf], bfl);                                  \
                        mma_bf16(c, al[mf], bfh);                                  \
                    }                                                              \
                }                                                                  \
            }                                                                      \
        }                                                                          \
    }

// root GEMM: g_out[n,:] = x[n,:] @ root  (plain store; scatter adds later)
__global__ __launch_bounds__(256, 2)
void k_gemm_root(int loff) {
    extern __shared__ char sm[];
    __nv_bfloat16* Ah = (__nv_bfloat16*)(sm + GSM_AH);
    __nv_bfloat16* Al = (__nv_bfloat16*)(sm + GSM_AL);
    __nv_bfloat16* Bh = (__nv_bfloat16*)(sm + GSM_BH);
    __nv_bfloat16* Bl = (__nv_bfloat16*)(sm + GSM_BL);

    const int tid  = threadIdx.x;
    const int lane = tid & 31, warp = tid >> 5;
    const int row0 = blockIdx.x * TM;

    for (int v = tid; v < 1024; v += 256) {            // A: 64 rows
        int r = v >> 4, c8 = (v & 15) << 3;
        int gr = row0 + r;
        uint4 h = make_uint4(0, 0, 0, 0), l = make_uint4(0, 0, 0, 0);
        if (gr < NN) {
            h = *(const uint4*)(g_xhi + (size_t)gr * DD + c8);
            l = *(const uint4*)(g_xlo + (size_t)gr * DD + c8);
        }
        *(uint4*)(Ah + r * PADK + c8) = h;
        *(uint4*)(Al + r * PADK + c8) = l;
    }
    for (int v = tid; v < 2048; v += 256) {            // B: 128 root rows of Wt
        int r = v >> 4, c8 = (v & 15) << 3;
        const size_t gofs = (size_t)loff + (size_t)(RR * DD + r) * DD + c8;
        *(uint4*)(Bh + r * PADK + c8) = *(const uint4*)(g_wthi + gofs);
        *(uint4*)(Bl + r * PADK + c8) = *(const uint4*)(g_wtlo + gofs);
    }
    __syncthreads();

    const int wm = warp & 1, wn = warp >> 1;
    const int a_row  = wm * 32 + (lane & 15);
    const int a_koff = (lane >> 4) * 8;
    const int b_nrow = wn * 32 + (lane & 7) + ((lane >> 3) & 1) * 8;
    const int b_koff = (lane >> 4) * 8;

    float acc[2][4][4];
#pragma unroll
    for (int i = 0; i < 2; i++)
#pragma unroll
        for (int j = 0; j < 4; j++)
#pragma unroll
            for (int k = 0; k < 4; k++) acc[i][j][k] = 0.f;

    MMA_CORE(Ah, Al, Bh, Bl, acc)

#pragma unroll
    for (int mf = 0; mf < 2; mf++) {
#pragma unroll
        for (int nf = 0; nf < 4; nf++) {
            int r = row0 + wm * 32 + mf * 16 + (lane >> 2);
            int c = wn * 32 + nf * 8 + (lane & 3) * 2;
            float* cc = acc[mf][nf];
            if (r < NN)
                *(float2*)(g_out + (size_t)r * DD + c) = make_float2(cc[0], cc[1]);
            if (r + 8 < NN)
                *(float2*)(g_out + (size_t)(r + 8) * DD + c) = make_float2(cc[2], cc[3]);
        }
    }
}

// relation GEMM + fused scatter over compacted virtual rows
__global__ __launch_bounds__(256, 2)
void k_gemm_rel(int loff) {
    if ((int)blockIdx.x >= g_nblk) return;
    extern __shared__ char sm[];
    __nv_bfloat16* Ah = (__nv_bfloat16*)(sm + GSM_AH);
    __nv_bfloat16* Al = (__nv_bfloat16*)(sm + GSM_AL);
    __nv_bfloat16* Bh = (__nv_bfloat16*)(sm + GSM_BH);
    __nv_bfloat16* Bl = (__nv_bfloat16*)(sm + GSM_BL);
    float*         hsm = (float*)(sm + GSM_BH);   // aliases B after MMA

    const int tid  = threadIdx.x;
    const int lane = tid & 31, warp = tid >> 5;
    const int row0 = blockIdx.x * TM;
    const int rel  = g_blockrel[blockIdx.x];

    for (int v = tid; v < 1024; v += 256) {            // A gather (64 virtual rows)
        int r = v >> 4, c8 = (v & 15) << 3;
        int node = g_vnode[row0 + r];
        uint4 h = make_uint4(0, 0, 0, 0), l = make_uint4(0, 0, 0, 0);
        if (node >= 0) {
            h = *(const uint4*)(g_xhi + (size_t)node * DD + c8);
            l = *(const uint4*)(g_xlo + (size_t)node * DD + c8);
        }
        *(uint4*)(Ah + r * PADK + c8) = h;
        *(uint4*)(Al + r * PADK + c8) = l;
    }
    for (int v = tid; v < 2048; v += 256) {            // B: relation's 128 Wt rows
        int r = v >> 4, c8 = (v & 15) << 3;
        const size_t gofs = (size_t)loff + (size_t)(rel * DD + r) * DD + c8;
        *(uint4*)(Bh + r * PADK + c8) = *(const uint4*)(g_wthi + gofs);
        *(uint4*)(Bl + r * PADK + c8) = *(const uint4*)(g_wtlo + gofs);
    }
    __syncthreads();

    const int wm = warp & 1, wn = warp >> 1;
    const int a_row  = wm * 32 + (lane & 15);
    const int a_koff = (lane >> 4) * 8;
    const int b_nrow = wn * 32 + (lane & 7) + ((lane >> 3) & 1) * 8;
    const int b_koff = (lane >> 4) * 8;

    float acc[2][4][4];
#pragma unroll
    for (int i = 0; i < 2; i++)
#pragma unroll
        for (int j = 0; j < 4; j++)
#pragma unroll
            for (int k = 0; k < 4; k++) acc[i][j][k] = 0.f;

    MMA_CORE(Ah, Al, Bh, Bl, acc)

    __syncthreads();   // all warps done reading B before hsm overwrites it

    // h tile -> smem (aliased over B)
#pragma unroll
    for (int mf = 0; mf < 2; mf++) {
#pragma unroll
        for (int nf = 0; nf < 4; nf++) {
            int r = wm * 32 + mf * 16 + (lane >> 2);
            int c = wn * 32 + nf * 8 + (lane & 3) * 2;
            float* cc = acc[mf][nf];
            *(float2*)(hsm + r * 128 + c)       = make_float2(cc[0], cc[1]);
            *(float2*)(hsm + (r + 8) * 128 + c) = make_float2(cc[2], cc[3]);
        }
    }
    __syncthreads();

    // scatter this block's edges (one warp per edge)
    int s = g_ptr[blockIdx.x], e2 = g_ptr[blockIdx.x + 1];
    for (int i = s + warp; i < e2; i += 8) {
        int   ls  = g_els[i];
        int   dst = g_ed[i];
        float inv = g_einv[i];
        float4 v = *(const float4*)(hsm + ls * 128 + lane * 4);
        v.x *= inv; v.y *= inv; v.z *= inv; v.w *= inv;
        red_add4(g_out + (size_t)dst * DD + lane * 4, v);
    }
}

// ---------------- activations (bias folded in) ----------------
__global__ void k_act_relu(const float* __restrict__ bias) {
    int t = blockIdx.x * blockDim.x + threadIdx.x;
    if (t >= NN * 32) return;
    float4 v = *(const float4*)(g_out + (size_t)t * 4);
    float4 b = __ldg((const float4*)(bias + (t & 31) * 4));
    v.x = fmaxf(v.x + b.x, 0.f); v.y = fmaxf(v.y + b.y, 0.f);
    v.z = fmaxf(v.z + b.z, 0.f); v.w = fmaxf(v.w + b.w, 0.f);
    __nv_bfloat16 h0, h1, h2, h3, l0, l1, l2, l3;
    split2(v.x, h0, l0); split2(v.y, h1, l1); split2(v.z, h2, l2); split2(v.w, h3, l3);
    __nv_bfloat162* ph = (__nv_bfloat162*)(g_xhi + (size_t)t * 4);
    __nv_bfloat162* pl = (__nv_bfloat162*)(g_xlo + (size_t)t * 4);
    ph[0] = __nv_bfloat162{h0, h1}; ph[1] = __nv_bfloat162{h2, h3};
    pl[0] = __nv_bfloat162{l0, l1}; pl[1] = __nv_bfloat162{l2, l3};
}

__global__ void k_sigmoid(const float* __restrict__ bias, float* __restrict__ outp) {
    int t = blockIdx.x * blockDim.x + threadIdx.x;
    if (t >= NN * 32) return;
    float4 v = *(const float4*)(g_out + (size_t)t * 4);
    float4 b = __ldg((const float4*)(bias + (t & 31) * 4));
    v.x = 1.0f / (1.0f + __expf(-(v.x + b.x)));
    v.y = 1.0f / (1.0f + __expf(-(v.y + b.y)));
    v.z = 1.0f / (1.0f + __expf(-(v.z + b.z)));
    v.w = 1.0f / (1.0f + __expf(-(v.w + b.w)));
    *(float4*)(outp + (size_t)t * 4) = v;
}

// ---------------- launch ----------------
extern "C" void kernel_launch(void* const* d_in, const int* in_sizes, int n_in,
                              void* d_out, int out_size) {
    const int*   x_ids = (const int*)  d_in[0];
    const int*   ei    = (const int*)  d_in[1];   // [2, E]: src row then dst row
    const int*   et    = (const int*)  d_in[2];
    const float* emb   = (const float*)d_in[3];
    const float* W1    = (const float*)d_in[4];
    const float* root1 = (const float*)d_in[5];
    const float* b1    = (const float*)d_in[6];
    const float* W2    = (const float*)d_in[7];
    const float* root2 = (const float*)d_in[8];
    const float* b2    = (const float*)d_in[9];
    float*       out   = (float*)d_out;
    (void)in_sizes; (void)n_in; (void)out_size;

    cudaFuncSetAttribute(k_gemm_rel,  cudaFuncAttributeMaxDynamicSharedMemorySize, GSM_TOTAL);
    cudaFuncSetAttribute(k_gemm_root, cudaFuncAttributeMaxDynamicSharedMemorySize, GSM_TOTAL);

    const int T = 256;

    // ---- prep ----
    k_gather_split<<<(NN * 32) / T, T>>>(x_ids, emb);
    k_wsplit<<<(KT * DD) / T, T>>>(W1, root1, 0);
    k_wsplit<<<(KT * DD) / T, T>>>(W2, root2, KT * DD);
    k_zero_prep<<<(NVROW + T - 1) / T, T>>>();
    k_hist2<<<(EE + T - 1) / T, T>>>(ei, et);
    k_inv_relnz<<<(NPAIR + T - 1) / T, T>>>();
    k_bases<<<1, 32>>>();
    k_blockrel<<<(MAXBLK + T - 1) / T, T>>>();
    k_compact<<<(NPAIR + T - 1) / T, T>>>();
    k_ehist<<<(EE + T - 1) / T, T>>>(ei, et);
    k_scan<<<1, 1024>>>();
    k_eperm<<<(EE + T - 1) / T, T>>>(ei, et);

    const int rootBlocks = (NN + TM - 1) / TM;   // 1563

    // ---- layer 1 ----
    k_gemm_root<<<rootBlocks, 256, GSM_TOTAL>>>(0);
    k_gemm_rel<<<MAXBLK, 256, GSM_TOTAL>>>(0);
    k_act_relu<<<(NN * 32) / T, T>>>(b1);

    // ---- layer 2 ----
    k_gemm_root<<<rootBlocks, 256, GSM_TOTAL>>>(KT * DD);
    k_gemm_rel<<<MAXBLK, 256, GSM_TOTAL>>>(KT * DD);
    k_sigmoid<<<(NN * 32) / T, T>>>(b2, out);
}